// round 5
// baseline (speedup 1.0000x reference)
#include <cuda_runtime.h>

#define NODES 100000
#define EDGES 640000
#define DIM   128
#define NDIN  239
#define NEG   0.01f
#define NB_SCAN 98   // ceil(NODES/1024)

// ---- scratch (__device__ globals; no allocs allowed) ----
__device__ float g_bufA[(size_t)NODES * DIM];
__device__ float g_bufB[(size_t)NODES * DIM];
__device__ float g_bufC[(size_t)NODES * DIM];
__device__ float g_dinv[NODES];
__device__ int   g_cnt[NODES];
__device__ int   g_start[NODES];
__device__ int   g_cursor[NODES];
__device__ int   g_bsum[NB_SCAN];
__device__ int   g_boff[NB_SCAN];
__device__ int   g_esrc[EDGES];
__device__ float g_enorm[EDGES];

// ---------------- CSR build ----------------
__global__ void k_init() {
    int i = blockIdx.x * blockDim.x + threadIdx.x;
    if (i < NODES) g_cnt[i] = 0;
}

__global__ void k_count(const int* __restrict__ ei) {
    int e = blockIdx.x * blockDim.x + threadIdx.x;
    if (e < EDGES) atomicAdd(&g_cnt[ei[EDGES + e]], 1);
}

__global__ void k_scan1() {               // 98 blocks x 1024
    __shared__ int sh[1024];
    int i = blockIdx.x * 1024 + threadIdx.x;
    int v = (i < NODES) ? g_cnt[i] : 0;
    sh[threadIdx.x] = v;
    __syncthreads();
#pragma unroll
    for (int off = 1; off < 1024; off <<= 1) {
        int t = (threadIdx.x >= off) ? sh[threadIdx.x - off] : 0;
        __syncthreads();
        sh[threadIdx.x] += t;
        __syncthreads();
    }
    if (i < NODES) g_start[i] = sh[threadIdx.x] - v;   // exclusive
    if (threadIdx.x == 1023) g_bsum[blockIdx.x] = sh[1023];
}

__global__ void k_scan2() {               // 1 block x 128
    __shared__ int sh[128];
    int v = (threadIdx.x < NB_SCAN) ? g_bsum[threadIdx.x] : 0;
    sh[threadIdx.x] = v;
    __syncthreads();
#pragma unroll
    for (int off = 1; off < 128; off <<= 1) {
        int t = (threadIdx.x >= off) ? sh[threadIdx.x - off] : 0;
        __syncthreads();
        sh[threadIdx.x] += t;
        __syncthreads();
    }
    if (threadIdx.x < NB_SCAN) g_boff[threadIdx.x] = sh[threadIdx.x] - v;
}

__global__ void k_scan3() {               // 98 blocks x 1024
    int i = blockIdx.x * 1024 + threadIdx.x;
    if (i < NODES) {
        int s = g_start[i] + g_boff[blockIdx.x];
        g_start[i] = s;
        g_cursor[i] = s;
        g_dinv[i] = rsqrtf((float)g_cnt[i] + 1.f);
    }
}

__global__ void k_fill(const int* __restrict__ ei) {
    int e = blockIdx.x * blockDim.x + threadIdx.x;
    if (e < EDGES) {
        int s = ei[e];
        int d = ei[EDGES + e];
        float n = g_dinv[s] * g_dinv[d];
        int pos = atomicAdd(&g_cursor[d], 1);
        g_esrc[pos] = s;
        g_enorm[pos] = n;
    }
}

// ---------------- f32x2 helpers ----------------
__device__ __forceinline__ unsigned long long pack_dup(float v) {
    unsigned long long p;
    asm("mov.b64 %0, {%1, %1};" : "=l"(p) : "f"(v));
    return p;
}
__device__ __forceinline__ unsigned long long pack2(float a, float b) {
    unsigned long long p;
    asm("mov.b64 %0, {%1, %2};" : "=l"(p) : "f"(a), "f"(b));
    return p;
}
__device__ __forceinline__ void unpack2(unsigned long long p, float& a, float& b) {
    asm("mov.b64 {%0, %1}, %2;" : "=f"(a), "=f"(b) : "l"(p));
}
#define FMA2(d, a, b) \
    asm("fma.rn.f32x2 %0, %1, %2, %0;" : "+l"(d) : "l"(a), "l"(b))

// ---------------- GEMM: out[M,128] = A[M,K] @ W[K,128] ----------------
// 128x128 block tile, 256 threads (16x16), 8x8 microtile, packed f32x2 FMA.
// LEAKY: out = leaky(acc + bias)
// CONV : out = acc (hw); agg = acc*dinv[row]^2 + bias  (self-loop fused)
template <bool LEAKY, bool CONV>
__global__ void __launch_bounds__(256)
k_gemm(const float* __restrict__ A, const float* __restrict__ W,
       const float* __restrict__ bias,
       float* __restrict__ out, float* __restrict__ agg,
       int M, int K) {
    __shared__ __align__(16) unsigned long long as_dup[16][129]; // (a,a) per [k][row]
    __shared__ __align__(16) unsigned long long ws[16][64];      // w pairs [k][col/2]

    int tx = threadIdx.x;            // 0..15 -> cols 8*tx .. 8*tx+7
    int ty = threadIdx.y;            // 0..15 -> rows ty + 16*i
    int tid = ty * 16 + tx;
    int row0 = blockIdx.x * 128;

    unsigned long long acc[8][4];
#pragma unroll
    for (int i = 0; i < 8; i++)
#pragma unroll
        for (int j = 0; j < 4; j++) acc[i][j] = 0ull;

    int nch = (K + 15) >> 4;
    for (int ch = 0; ch < nch; ch++) {
        int k0 = ch << 4;
        // A tile: 128 rows x 16 cols -> duplicated pairs, [k][row] layout
#pragma unroll
        for (int j = 0; j < 8; j++) {
            int idx = tid + 256 * j;
            int c = idx & 15, r = idx >> 4;
            int gr = row0 + r, gc = k0 + c;
            float v = (gr < M && gc < K) ? A[(long)gr * K + gc] : 0.f;
            as_dup[c][r] = pack_dup(v);
        }
        // W tile: 16 x 128 floats -> packed pairs
#pragma unroll
        for (int j = 0; j < 2; j++) {
            int idx = tid + 256 * j;       // float4 index 0..511
            int k = idx >> 5, c4 = idx & 31;
            float4 v = make_float4(0.f, 0.f, 0.f, 0.f);
            if (k0 + k < K) v = *(const float4*)&W[(long)(k0 + k) * 128 + c4 * 4];
            ws[k][c4 * 2]     = pack2(v.x, v.y);
            ws[k][c4 * 2 + 1] = pack2(v.z, v.w);
        }
        __syncthreads();
#pragma unroll
        for (int k = 0; k < 16; k++) {
            ulonglong2 w01 = *(ulonglong2*)&ws[k][tx * 4];
            ulonglong2 w23 = *(ulonglong2*)&ws[k][tx * 4 + 2];
#pragma unroll
            for (int i = 0; i < 8; i++) {
                unsigned long long a = as_dup[k][ty + 16 * i];
                FMA2(acc[i][0], a, w01.x);
                FMA2(acc[i][1], a, w01.y);
                FMA2(acc[i][2], a, w23.x);
                FMA2(acc[i][3], a, w23.y);
            }
        }
        __syncthreads();
    }

    int cb = tx * 8;
    float4 b0 = *(const float4*)&bias[cb];
    float4 b1 = *(const float4*)&bias[cb + 4];
#pragma unroll
    for (int i = 0; i < 8; i++) {
        int r = row0 + ty + 16 * i;
        if (r >= M) continue;
        float4 v0, v1;
        unpack2(acc[i][0], v0.x, v0.y);
        unpack2(acc[i][1], v0.z, v0.w);
        unpack2(acc[i][2], v1.x, v1.y);
        unpack2(acc[i][3], v1.z, v1.w);
        long base = (long)r * 128 + cb;
        if (CONV) {
            *(float4*)&out[base]     = v0;   // hw for gather
            *(float4*)&out[base + 4] = v1;
            float di = g_dinv[r];
            float s = di * di;
            float4 a0 = make_float4(fmaf(v0.x, s, b0.x), fmaf(v0.y, s, b0.y),
                                    fmaf(v0.z, s, b0.z), fmaf(v0.w, s, b0.w));
            float4 a1 = make_float4(fmaf(v1.x, s, b1.x), fmaf(v1.y, s, b1.y),
                                    fmaf(v1.z, s, b1.z), fmaf(v1.w, s, b1.w));
            *(float4*)&agg[base]     = a0;
            *(float4*)&agg[base + 4] = a1;
        } else {
            v0.x += b0.x; v0.y += b0.y; v0.z += b0.z; v0.w += b0.w;
            v1.x += b1.x; v1.y += b1.y; v1.z += b1.z; v1.w += b1.w;
            if (LEAKY) {
                v0.x = fmaxf(v0.x, NEG * v0.x); v0.y = fmaxf(v0.y, NEG * v0.y);
                v0.z = fmaxf(v0.z, NEG * v0.z); v0.w = fmaxf(v0.w, NEG * v0.w);
                v1.x = fmaxf(v1.x, NEG * v1.x); v1.y = fmaxf(v1.y, NEG * v1.y);
                v1.z = fmaxf(v1.z, NEG * v1.z); v1.w = fmaxf(v1.w, NEG * v1.w);
            }
            *(float4*)&out[base]     = v0;
            *(float4*)&out[base + 4] = v1;
        }
    }
}

// ---------------- CSR aggregation: agg[d] += sum_e hw[src(e)]*norm(e) ----------------
// One warp per node, lane c handles float4; plain stores, no atomics.
__global__ void k_gather(const float* __restrict__ hw, float* __restrict__ agg) {
    int idx = blockIdx.x * blockDim.x + threadIdx.x;
    int node = idx >> 5;
    int c = (idx & 31) * 4;
    if (node >= NODES) return;
    int s0 = g_start[node];
    int cnt = g_cnt[node];
    long base = (long)node * 128 + c;
    float4 acc = *(const float4*)&agg[base];
    for (int j = 0; j < cnt; j++) {
        int src = __ldg(&g_esrc[s0 + j]);
        float n = __ldg(&g_enorm[s0 + j]);
        const float4 v = *(const float4*)&hw[(long)src * 128 + c];
        acc.x = fmaf(v.x, n, acc.x);
        acc.y = fmaf(v.y, n, acc.y);
        acc.z = fmaf(v.z, n, acc.z);
        acc.w = fmaf(v.w, n, acc.w);
    }
    *(float4*)&agg[base] = acc;
}

// ---------------- final projection: out[M,2] = h[M,128] @ W[128,2] + b ----------------
__global__ void k_out(const float* __restrict__ h, const float* __restrict__ W,
                      const float* __restrict__ b, float* __restrict__ out) {
    __shared__ float ws[256];
    int tid = threadIdx.x;
    if (tid < 256) ws[tid] = W[tid];
    __syncthreads();
    int warp = (blockIdx.x * blockDim.x + tid) >> 5;
    int lane = tid & 31;
    if (warp >= NODES) return;
    float4 v = *(const float4*)&h[(long)warp * 128 + lane * 4];
    int k = lane * 4;
    float s0 = v.x * ws[(k + 0) * 2] + v.y * ws[(k + 1) * 2] +
               v.z * ws[(k + 2) * 2] + v.w * ws[(k + 3) * 2];
    float s1 = v.x * ws[(k + 0) * 2 + 1] + v.y * ws[(k + 1) * 2 + 1] +
               v.z * ws[(k + 2) * 2 + 1] + v.w * ws[(k + 3) * 2 + 1];
#pragma unroll
    for (int o = 16; o; o >>= 1) {
        s0 += __shfl_xor_sync(0xFFFFFFFFu, s0, o);
        s1 += __shfl_xor_sync(0xFFFFFFFFu, s1, o);
    }
    if (lane == 0) {
        out[(long)warp * 2 + 0] = s0 + b[0];
        out[(long)warp * 2 + 1] = s1 + b[1];
    }
}

// ---------------- launch ----------------
extern "C" void kernel_launch(void* const* d_in, const int* in_sizes, int n_in,
                              void* d_out, int out_size) {
    int ix, iei, iwin, ibin, iwg, ibg, iwo1, ibo1, iwo2, ibo2;
    if (in_sizes[0] == 16384) {          // alphabetical (hedge)
        iwg = 0; iwin = 1; iwo1 = 2; iwo2 = 3;
        ibg = 4; ibin = 5; ibo1 = 6; ibo2 = 7;
        iei = 8; ix = 10;
    } else {                              // dict / insertion order
        ix = 0; iei = 1;
        iwin = 3; ibin = 4; iwg = 5; ibg = 6;
        iwo1 = 7; ibo1 = 8; iwo2 = 9; ibo2 = 10;
    }

    const float* x    = (const float*)d_in[ix];
    const int*   ei   = (const int*)d_in[iei];   // int32 (JAX x64 disabled)
    const float* W_in = (const float*)d_in[iwin];
    const float* b_in = (const float*)d_in[ibin];
    const float* W_g  = (const float*)d_in[iwg];
    const float* b_g  = (const float*)d_in[ibg];
    const float* W_o1 = (const float*)d_in[iwo1];
    const float* b_o1 = (const float*)d_in[ibo1];
    const float* W_o2 = (const float*)d_in[iwo2];
    const float* b_o2 = (const float*)d_in[ibo2];
    float* out = (float*)d_out;

    float *bufA, *bufB, *bufC;
    cudaGetSymbolAddress((void**)&bufA, g_bufA);
    cudaGetSymbolAddress((void**)&bufB, g_bufB);
    cudaGetSymbolAddress((void**)&bufC, g_bufC);

    dim3 gblk(16, 16);
    int gemm_grid = (NODES + 127) / 128;
    int gath_grid = (NODES * 32 + 255) / 256;

    // CSR build (launches 1-5), then big GEMM as launch #6 (ncu -s 5 target)
    k_init<<<(NODES + 255) / 256, 256>>>();
    k_count<<<(EDGES + 255) / 256, 256>>>(ei);
    k_scan1<<<NB_SCAN, 1024>>>();
    k_scan2<<<1, 128>>>();
    k_scan3<<<NB_SCAN, 1024>>>();

    // h0 = leaky(x @ W_in + b_in)            -> bufA
    k_gemm<true, false><<<gemm_grid, gblk>>>(x, W_in, b_in, bufA, nullptr, NODES, NDIN);

    k_fill<<<(EDGES + 255) / 256, 256>>>(ei);

    // conv1: hw -> bufB ; agg(self+bias) -> bufC ; gather into bufC
    k_gemm<false, true><<<gemm_grid, gblk>>>(bufA, W_g, b_g, bufB, bufC, NODES, DIM);
    k_gather<<<gath_grid, 256>>>(bufB, bufC);

    // conv2: hw -> bufB ; agg -> bufA ; gather into bufA
    k_gemm<false, true><<<gemm_grid, gblk>>>(bufC, W_g, b_g, bufB, bufA, NODES, DIM);
    k_gather<<<gath_grid, 256>>>(bufB, bufA);

    // h3 = leaky(bufA @ W_o1 + b_o1)         -> bufC
    k_gemm<true, false><<<gemm_grid, gblk>>>(bufA, W_o1, b_o1, bufC, nullptr, NODES, DIM);

    // out = bufC @ W_o2 + b_o2
    k_out<<<(NODES * 32 + 255) / 256, 256>>>(bufC, W_o2, b_o2, out);
}